// round 12
// baseline (speedup 1.0000x reference)
#include <cuda_runtime.h>

#define NPTS 16384
#define NS   8192
#define KNB  10
#define R2   0.0625f
#define NGRP 256
#define GSZ  64
#define GDIM 8
#define NCELL (GDIM * GDIM * GDIM)
#define CPB  32
#define GPW  16           // groups per warp (16 warps x 16 = 256)
#define NW   16           // warps

typedef unsigned long long ull;

// ---------------- global scratch (no allocation allowed) ----------------
__device__ __align__(16) float g_px[NPTS];   // original order SoA
__device__ __align__(16) float g_py[NPTS];
__device__ __align__(16) float g_pz[NPTS];
__device__ __align__(16) float g_sx[NPTS];   // spatially sorted SoA
__device__ __align__(16) float g_sy[NPTS];
__device__ __align__(16) float g_sz[NPTS];
__device__ __align__(16) int   g_sidx[NPTS]; // sorted slot -> original index
__device__ int g_cellcnt[NCELL];
__device__ int g_cellcur[NCELL];
__device__ float4 g_boxa[NGRP];              // {minx,miny,minz, FLT_MAX(gmax)}
__device__ float4 g_boxb[NGRP];              // {maxx,maxy,maxz, 0}
__device__ float g_cx[NS], g_cy[NS], g_cz[NS];
__device__ int   g_src[NS * KNB];

// ---------------- packed f32x2 helpers (bit-exact IEEE RN per lane) ------
__device__ __forceinline__ ull f2_add(ull a, ull b) {
    ull r; asm("add.rn.f32x2 %0, %1, %2;" : "=l"(r) : "l"(a), "l"(b)); return r;
}
__device__ __forceinline__ ull f2_mul(ull a, ull b) {
    ull r; asm("mul.rn.f32x2 %0, %1, %2;" : "=l"(r) : "l"(a), "l"(b)); return r;
}
__device__ __forceinline__ ull pack2(unsigned lo, unsigned hi) {
    ull r; asm("mov.b64 %0, {%1, %2};" : "=l"(r) : "r"(lo), "r"(hi)); return r;
}
__device__ __forceinline__ void unpack2(unsigned &lo, unsigned &hi, ull v) {
    asm("mov.b64 {%0, %1}, %2;" : "=r"(lo), "=r"(hi) : "l"(v));
}
__device__ __forceinline__ ull umax64(ull a, ull b) { return a > b ? a : b; }
__device__ __forceinline__ ull umin64(ull a, ull b) { return a < b ? a : b; }
__device__ __forceinline__ int cell_of(float x, float y, float z) {
    int cx = min(GDIM - 1, (int)(x * (float)GDIM));
    int cy = min(GDIM - 1, (int)(y * (float)GDIM));
    int cz = min(GDIM - 1, (int)(z * (float)GDIM));
    return (cz * GDIM + cy) * GDIM + cx;
}

// ---------------- K0: AoS -> SoA + zero counters ----------------
__global__ void prep_kernel(const float* __restrict__ pos) {
    int i = blockIdx.x * blockDim.x + threadIdx.x;
    if (i < NCELL) g_cellcnt[i] = 0;
    if (i < NPTS) {
        g_px[i] = pos[3 * i + 0];
        g_py[i] = pos[3 * i + 1];
        g_pz[i] = pos[3 * i + 2];
    }
}
// ---------------- K0b: histogram ----------------
__global__ void hist_kernel() {
    int i = blockIdx.x * blockDim.x + threadIdx.x;
    if (i < NPTS) atomicAdd(&g_cellcnt[cell_of(g_px[i], g_py[i], g_pz[i])], 1);
}
// ---------------- K0c: exclusive scan of cell counts (1 block) ----------------
__global__ __launch_bounds__(NCELL) void scan_kernel() {
    __shared__ int wsum[NCELL / 32];
    int tid = threadIdx.x, lane = tid & 31, wid = tid >> 5;
    int v = g_cellcnt[tid];
    int x = v;
#pragma unroll
    for (int o = 1; o < 32; o <<= 1) {
        int y = __shfl_up_sync(0xffffffffu, x, o);
        if (lane >= o) x += y;
    }
    if (lane == 31) wsum[wid] = x;
    __syncthreads();
    if (wid == 0) {
        int s = (lane < NCELL / 32) ? wsum[lane] : 0;
#pragma unroll
        for (int o = 1; o < 32; o <<= 1) {
            int y = __shfl_up_sync(0xffffffffu, s, o);
            if (lane >= o) s += y;
        }
        if (lane < NCELL / 32) wsum[lane] = s;
    }
    __syncthreads();
    int pre = (wid > 0) ? wsum[wid - 1] : 0;
    g_cellcur[tid] = pre + x - v;
}
// ---------------- K0d: scatter into sorted order ----------------
__global__ void scatter_kernel() {
    int i = blockIdx.x * blockDim.x + threadIdx.x;
    if (i < NPTS) {
        float x = g_px[i], y = g_py[i], z = g_pz[i];
        int slot = atomicAdd(&g_cellcur[cell_of(x, y, z)], 1);
        g_sx[slot] = x; g_sy[slot] = y; g_sz[slot] = z;
        g_sidx[slot] = i;
    }
}
// ---------------- K0e: per-group bounding boxes (1 warp / group) ----------------
__global__ __launch_bounds__(256) void boxes_kernel() {
    const int lane = threadIdx.x & 31;
    const int g = blockIdx.x * 8 + (threadIdx.x >> 5);
    const int base = g * GSZ + 2 * lane;
    float2 x2 = *(const float2*)&g_sx[base];
    float2 y2 = *(const float2*)&g_sy[base];
    float2 z2 = *(const float2*)&g_sz[base];
    unsigned mnx = __reduce_min_sync(0xffffffffu, min(__float_as_uint(x2.x), __float_as_uint(x2.y)));
    unsigned mxx = __reduce_max_sync(0xffffffffu, max(__float_as_uint(x2.x), __float_as_uint(x2.y)));
    unsigned mny = __reduce_min_sync(0xffffffffu, min(__float_as_uint(y2.x), __float_as_uint(y2.y)));
    unsigned mxy = __reduce_max_sync(0xffffffffu, max(__float_as_uint(y2.x), __float_as_uint(y2.y)));
    unsigned mnz = __reduce_min_sync(0xffffffffu, min(__float_as_uint(z2.x), __float_as_uint(z2.y)));
    unsigned mxz = __reduce_max_sync(0xffffffffu, max(__float_as_uint(z2.x), __float_as_uint(z2.y)));
    if (lane == 0) {
        g_boxa[g] = make_float4(__uint_as_float(mnx), __uint_as_float(mny),
                                __uint_as_float(mnz), 3.402823466e38f);
        g_boxb[g] = make_float4(__uint_as_float(mxx), __uint_as_float(mxy),
                                __uint_as_float(mxz), 0.0f);
    }
}

// ---------------- K1: FPS — no warp-best stage; direct 256-group fold ---------
// Warp w owns groups {j*16 + w} (interleaved -> balanced update). Keys in regs:
// key = (min_d_bits<<32)|~orig_idx; u64 max = max d2, tie -> min original
// index == jnp.argmax (keys globally unique). d2 = ((dx*dx+dy*dy)+dz*dz) in
// RN ops, no FMA (bit-exact vs XLA). Update maintains per-group max key
// (s_gkey) + winner coords (s_gwin) + prune bound (boxa.w) incrementally, so
// after ONE barrier every warp folds the 256 group keys directly (8/lane) —
// no intermediate warp-best handoff. Groups skipped only when a conservative
// bound proves the update is a no-op.
__global__ __launch_bounds__(512, 1) void fps_kernel() {
    extern __shared__ unsigned char smem_raw[];
    ull*    s_x2   = (ull*)smem_raw;               // [NPTS/2]  64KB
    ull*    s_y2   = s_x2 + NPTS / 2;              // 64KB
    ull*    s_z2   = s_y2 + NPTS / 2;              // 64KB
    ull*    s_gkey = s_z2 + NPTS / 2;              // [NGRP] owner-local phys
    float4* s_boxa = (float4*)(s_gkey + NGRP);     // [NGRP] owner-local {min,gmax}
    float4* s_boxb = s_boxa + NGRP;                // [NGRP] owner-local
    float4* s_gwin = s_boxb + NGRP;                // [NGRP] owner-local argmax pt

    const int tid  = threadIdx.x;
    const int lane = tid & 31;
    const int w    = tid >> 5;

    // ---- stage coords into smem; keys into registers ----
    for (int i = tid; i < NPTS / 2; i += 512) {
        s_x2[i] = ((const ull*)g_sx)[i];
        s_y2[i] = ((const ull*)g_sy)[i];
        s_z2[i] = ((const ull*)g_sz)[i];
    }
    ull K0[GPW], K1[GPW];
#pragma unroll
    for (int j = 0; j < GPW; j++) {
        const int g = j * NW + w;                  // logical group (interleaved)
        const int p = g * GSZ + 2 * lane;
        int2 si = *(const int2*)&g_sidx[p];
        K0[j] = (0x7f7fffffULL << 32) | (unsigned)(~si.x);
        K1[j] = (0x7f7fffffULL << 32) | (unsigned)(~si.y);
    }
    if (tid < NGRP) {
        // phys tid = w0*16 + j0  <->  logical group j0*16 + w0
        const int gl = (tid & (GPW - 1)) * NW + (tid >> 4);
        s_boxa[tid] = g_boxa[gl];                  // .w = FLT_MAX (gmax)
        s_boxb[tid] = g_boxb[gl];
        s_gkey[tid] = 0;                           // set at step 0 (all active)
        s_gwin[tid] = make_float4(0.f, 0.f, 0.f, 0.f);
    }
    float cx = g_px[0], cy = g_py[0], cz = g_pz[0];
    if (tid == 0) { g_cx[0] = cx; g_cy[0] = cy; g_cz[0] = cz; }
    __syncthreads();

    for (int s = 0; s < NS - 1; s++) {
        // ---- prune: lane j (<16) tests box phys w*16+j ----
        bool act = false;
        if (lane < GPW) {
            const int ph = w * GPW + lane;
            float4 a = s_boxa[ph];
            float4 b = s_boxb[ph];
            float dx = fmaxf(fmaxf(a.x - cx, cx - b.x), 0.0f);
            float dy = fmaxf(fmaxf(a.y - cy, cy - b.y), 0.0f);
            float dz = fmaxf(fmaxf(a.z - cz, cz - b.z), 0.0f);
            float lb = dx * dx + dy * dy + dz * dz;
            act = (lb * 0.99999f - 1e-6f < a.w);
        }
        const unsigned amask = __ballot_sync(0xffffffffu, act);

        if (amask) {
            // ---- update active groups (keys in regs, coords via LDS) ----
            const unsigned nbx = __float_as_uint(-cx);
            const unsigned nby = __float_as_uint(-cy);
            const unsigned nbz = __float_as_uint(-cz);
            const ull nlx = pack2(nbx, nbx);
            const ull nly = pack2(nby, nby);
            const ull nlz = pack2(nbz, nbz);
#pragma unroll
            for (int j = 0; j < GPW; j++) {
                if ((amask >> j) & 1u) {           // warp-uniform branch
                    const int pp = (j * NW + w) * 32 + lane;   // point-pair idx
                    const ull X = s_x2[pp];
                    const ull Y = s_y2[pp];
                    const ull Z = s_z2[pp];
                    ull dx = f2_add(X, nlx);       // x - cx, exact RN
                    ull dy = f2_add(Y, nly);
                    ull dz = f2_add(Z, nlz);
                    ull d2 = f2_add(f2_add(f2_mul(dx, dx), f2_mul(dy, dy)), f2_mul(dz, dz));
                    unsigned d0, d1; unpack2(d0, d1, d2);
                    K0[j] = umin64(K0[j], ((ull)d0 << 32) | (unsigned)K0[j]);
                    K1[j] = umin64(K1[j], ((ull)d1 << 32) | (unsigned)K1[j]);
                    ull m = umax64(K0[j], K1[j]);
                    unsigned hi = (unsigned)(m >> 32);
                    unsigned gm = __reduce_max_sync(0xffffffffu, hi);
                    unsigned cand = __ballot_sync(0xffffffffu, hi == gm);
                    bool win;
                    if (__popc(cand) == 1) {       // unique hi winner (common)
                        win = (hi == gm);
                    } else {                       // exact u64 tie-break on lo
                        unsigned lc = (hi == gm) ? (unsigned)m : 0u;
                        unsigned gl = __reduce_max_sync(0xffffffffu, lc);
                        unsigned wb = __ballot_sync(0xffffffffu, hi == gm && (unsigned)m == gl);
                        win = (lane == (__ffs(wb) - 1));
                    }
                    if (win) {                     // group argmax owner
                        const int ph = w * GPW + j;
                        const bool first = (m == K0[j]);
                        unsigned xl, xh, yl, yh, zl, zh;
                        unpack2(xl, xh, X); unpack2(yl, yh, Y); unpack2(zl, zh, Z);
                        s_gwin[ph] = make_float4(__uint_as_float(first ? xl : xh),
                                                 __uint_as_float(first ? yl : yh),
                                                 __uint_as_float(first ? zl : zh), 0.f);
                        s_gkey[ph] = m;
                        s_boxa[ph].w = __uint_as_float(gm);   // refresh gmax
                    }
                }
            }
        }
        __syncthreads();                           // the ONE barrier

        // ---- global best: direct fold over 256 group keys (every warp) ----
        ull best = s_gkey[lane];
        int  bph = lane;
#pragma unroll
        for (int j = 1; j < 8; j++) {
            ull kk = s_gkey[j * 32 + lane];
            if (kk > best) { best = kk; bph = j * 32 + lane; }
        }
        unsigned bh = (unsigned)(best >> 32);
        unsigned gm2 = __reduce_max_sync(0xffffffffu, bh);
        unsigned cand2 = __ballot_sync(0xffffffffu, bh == gm2);
        if (__popc(cand2) != 1) {                  // rare hi tie across lanes
            unsigned lc2 = (bh == gm2) ? (unsigned)best : 0u;
            unsigned gl2 = __reduce_max_sync(0xffffffffu, lc2);
            cand2 = __ballot_sync(0xffffffffu, bh == gm2 && (unsigned)best == gl2);
        }
        const int src = __ffs(cand2) - 1;
        const int ph  = __shfl_sync(0xffffffffu, bph, src);   // winner group
        float4 c4 = s_gwin[ph];                    // uniform LDS broadcast
        cx = c4.x; cy = c4.y; cz = c4.z;
        if (tid == 0) { g_cx[s + 1] = cx; g_cy[s + 1] = cy; g_cz[s + 1] = cz; }
    }
}

// ---------------- K2: top-10 nearest per center (1 warp / center) ----------------
__global__ __launch_bounds__(256) void topk_kernel() {
    const int lane = threadIdx.x & 31;
    const int w    = threadIdx.x >> 5;
    const int c    = blockIdx.x * 8 + w;
    const float cx = g_cx[c], cy = g_cy[c], cz = g_cz[c];

    ull heap[KNB];  // sorted ascending; key = (d2_bits<<32)|idx
#pragma unroll
    for (int q = 0; q < KNB; q++) heap[q] = ~0ULL;

#pragma unroll 4
    for (int i = 0; i < NPTS / 32; i++) {
        int p = lane + 32 * i;
        float dx = __fsub_rn(cx, __ldg(&g_px[p]));
        float dy = __fsub_rn(cy, __ldg(&g_py[p]));
        float dz = __fsub_rn(cz, __ldg(&g_pz[p]));
        float d2 = __fadd_rn(__fadd_rn(__fmul_rn(dx, dx), __fmul_rn(dy, dy)), __fmul_rn(dz, dz));
        ull key = ((ull)__float_as_uint(d2) << 32) | (unsigned)p;
        if (key < heap[KNB - 1]) {
            heap[KNB - 1] = key;
#pragma unroll
            for (int q = KNB - 1; q > 0; q--) {
                ull a = heap[q - 1], b = heap[q];
                heap[q - 1] = (a < b) ? a : b;
                heap[q]     = (a < b) ? b : a;
            }
        }
    }
#pragma unroll
    for (int r = 0; r < KNB; r++) {
        ull cur = heap[0];
        unsigned hi = (unsigned)(cur >> 32);
        unsigned mh = __reduce_min_sync(0xffffffffu, hi);
        unsigned lo = (hi == mh) ? (unsigned)cur : 0xffffffffu;
        unsigned ml = __reduce_min_sync(0xffffffffu, lo);
        if (hi == mh && (unsigned)cur == ml) {
#pragma unroll
            for (int q = 0; q < KNB - 1; q++) heap[q] = heap[q + 1];
            heap[KNB - 1] = ~0ULL;
        }
        if (lane == 0)
            g_src[c * KNB + r] = (__uint_as_float(mh) <= R2) ? (int)ml : -1;
    }
}

// ---------------- K3: MLP + masked segment max (CPB centers / block) ----------------
__global__ __launch_bounds__(128) void mlp_kernel(const float* __restrict__ W1,
                                                  const float* __restrict__ b1,
                                                  const float* __restrict__ W2,
                                                  const float* __restrict__ b2,
                                                  float* __restrict__ out) {
    const int c0 = blockIdx.x * CPB;
    const int t  = threadIdx.x;
    __shared__ float s_w2[64 * 128];
    __shared__ float s_hid[64];
    __shared__ int   s_src[CPB * KNB];

#pragma unroll
    for (int q = 0; q < 64; q++) s_w2[q * 128 + t] = W2[q * 128 + t];
    for (int i = t; i < CPB * KNB; i += 128) s_src[i] = g_src[c0 * KNB + i];

    float w1a = 0.f, w1b = 0.f, w1c = 0.f, bb1 = 0.f;
    if (t < 64) { w1a = W1[t]; w1b = W1[64 + t]; w1c = W1[128 + t]; bb1 = b1[t]; }
    const float b2c = b2[t];
    __syncthreads();

    for (int cc = 0; cc < CPB; cc++) {
        const int c = c0 + cc;
        const float bx = g_px[c], by = g_py[c], bz = g_pz[c];
        float acc = -3.402823466e38f;
        bool any = false;
        for (int nb = 0; nb < KNB; nb++) {
            int sp = s_src[cc * KNB + nb];
            if (sp >= 0) {
                any = true;
                if (t < 64) {
                    float rx = g_px[sp] - bx, ry = g_py[sp] - by, rz = g_pz[sp] - bz;
                    float h = bb1 + rx * w1a + ry * w1b + rz * w1c;
                    s_hid[t] = h > 0.f ? h : 0.f;
                }
                __syncthreads();
                float a = b2c;
#pragma unroll
                for (int k = 0; k < 64; k++) a = fmaf(s_hid[k], s_w2[k * 128 + t], a);
                acc = fmaxf(acc, a);
                __syncthreads();
            }
        }
        out[c * 128 + t] = any ? acc : 0.0f;
    }
}

// ---------------- K4: zero-fill rows NS..NPTS-1 ----------------
__global__ void fill_kernel(float* __restrict__ out) {
    int i = blockIdx.x * blockDim.x + threadIdx.x;
    if (i < (NPTS - NS) * 128) out[NS * 128 + i] = 0.0f;
}

// ---------------- launch ----------------
extern "C" void kernel_launch(void* const* d_in, const int* in_sizes, int n_in,
                              void* d_out, int out_size) {
    const float* pos = (const float*)d_in[0];
    const float* W1 = (const float*)d_in[2];
    const float* b1 = (const float*)d_in[3];
    const float* W2 = (const float*)d_in[4];
    const float* b2 = (const float*)d_in[5];
    float* out = (float*)d_out;

    prep_kernel<<<(NPTS + 255) / 256, 256>>>(pos);
    hist_kernel<<<(NPTS + 255) / 256, 256>>>();
    scan_kernel<<<1, NCELL>>>();
    scatter_kernel<<<(NPTS + 255) / 256, 256>>>();
    boxes_kernel<<<NGRP / 8, 256>>>();

    const int fps_smem = 3 * (NPTS / 2) * 8        // coords
                       + NGRP * 8                  // s_gkey
                       + NGRP * 16 * 3;            // s_boxa, s_boxb, s_gwin
    cudaFuncSetAttribute(fps_kernel, cudaFuncAttributeMaxDynamicSharedMemorySize, fps_smem);
    fps_kernel<<<1, 512, fps_smem>>>();

    topk_kernel<<<NS / 8, 256>>>();

    mlp_kernel<<<NS / CPB, 128>>>(W1, b1, W2, b2, out);
    fill_kernel<<<((NPTS - NS) * 128 + 255) / 256, 256>>>(out);
}

// round 14
// speedup vs baseline: 1.1316x; 1.1316x over previous
#include <cuda_runtime.h>

#define NPTS 16384
#define NS   8192
#define KNB  10
#define R2   0.0625f
#define NGRP 256
#define GSZ  64
#define GDIM 8
#define NCELL (GDIM * GDIM * GDIM)
#define CPB  32
#define GPW  16           // groups per warp (16 warps x 16 = 256)
#define NW   16           // warps

typedef unsigned long long ull;

// ---------------- global scratch (no allocation allowed) ----------------
__device__ __align__(16) float g_px[NPTS];   // original order SoA
__device__ __align__(16) float g_py[NPTS];
__device__ __align__(16) float g_pz[NPTS];
__device__ __align__(16) float g_sx[NPTS];   // spatially sorted SoA
__device__ __align__(16) float g_sy[NPTS];
__device__ __align__(16) float g_sz[NPTS];
__device__ __align__(16) int   g_sidx[NPTS]; // sorted slot -> original index
__device__ int g_cellcnt[NCELL];
__device__ int g_cellcur[NCELL];
__device__ float4 g_boxa[NGRP];              // {minx,miny,minz, -}
__device__ float4 g_boxb[NGRP];              // {maxx,maxy,maxz, -}
__device__ float g_cx[NS], g_cy[NS], g_cz[NS];
__device__ int   g_src[NS * KNB];

// ---------------- packed f32x2 helpers (bit-exact IEEE RN per lane) ------
__device__ __forceinline__ ull f2_add(ull a, ull b) {
    ull r; asm("add.rn.f32x2 %0, %1, %2;" : "=l"(r) : "l"(a), "l"(b)); return r;
}
__device__ __forceinline__ ull f2_mul(ull a, ull b) {
    ull r; asm("mul.rn.f32x2 %0, %1, %2;" : "=l"(r) : "l"(a), "l"(b)); return r;
}
__device__ __forceinline__ ull pack2(unsigned lo, unsigned hi) {
    ull r; asm("mov.b64 %0, {%1, %2};" : "=l"(r) : "r"(lo), "r"(hi)); return r;
}
__device__ __forceinline__ void unpack2(unsigned &lo, unsigned &hi, ull v) {
    asm("mov.b64 {%0, %1}, %2;" : "=r"(lo), "=r"(hi) : "l"(v));
}
__device__ __forceinline__ ull umax64(ull a, ull b) { return a > b ? a : b; }
__device__ __forceinline__ ull umin64(ull a, ull b) { return a < b ? a : b; }
__device__ __forceinline__ int cell_of(float x, float y, float z) {
    int cx = min(GDIM - 1, (int)(x * (float)GDIM));
    int cy = min(GDIM - 1, (int)(y * (float)GDIM));
    int cz = min(GDIM - 1, (int)(z * (float)GDIM));
    return (cz * GDIM + cy) * GDIM + cx;
}

// ---------------- K0: AoS -> SoA + zero counters ----------------
__global__ void prep_kernel(const float* __restrict__ pos) {
    int i = blockIdx.x * blockDim.x + threadIdx.x;
    if (i < NCELL) g_cellcnt[i] = 0;
    if (i < NPTS) {
        g_px[i] = pos[3 * i + 0];
        g_py[i] = pos[3 * i + 1];
        g_pz[i] = pos[3 * i + 2];
    }
}
// ---------------- K0b: histogram ----------------
__global__ void hist_kernel() {
    int i = blockIdx.x * blockDim.x + threadIdx.x;
    if (i < NPTS) atomicAdd(&g_cellcnt[cell_of(g_px[i], g_py[i], g_pz[i])], 1);
}
// ---------------- K0c: exclusive scan of cell counts (1 block) ----------------
__global__ __launch_bounds__(NCELL) void scan_kernel() {
    __shared__ int wsum[NCELL / 32];
    int tid = threadIdx.x, lane = tid & 31, wid = tid >> 5;
    int v = g_cellcnt[tid];
    int x = v;
#pragma unroll
    for (int o = 1; o < 32; o <<= 1) {
        int y = __shfl_up_sync(0xffffffffu, x, o);
        if (lane >= o) x += y;
    }
    if (lane == 31) wsum[wid] = x;
    __syncthreads();
    if (wid == 0) {
        int s = (lane < NCELL / 32) ? wsum[lane] : 0;
#pragma unroll
        for (int o = 1; o < 32; o <<= 1) {
            int y = __shfl_up_sync(0xffffffffu, s, o);
            if (lane >= o) s += y;
        }
        if (lane < NCELL / 32) wsum[lane] = s;
    }
    __syncthreads();
    int pre = (wid > 0) ? wsum[wid - 1] : 0;
    g_cellcur[tid] = pre + x - v;
}
// ---------------- K0d: scatter into sorted order ----------------
__global__ void scatter_kernel() {
    int i = blockIdx.x * blockDim.x + threadIdx.x;
    if (i < NPTS) {
        float x = g_px[i], y = g_py[i], z = g_pz[i];
        int slot = atomicAdd(&g_cellcur[cell_of(x, y, z)], 1);
        g_sx[slot] = x; g_sy[slot] = y; g_sz[slot] = z;
        g_sidx[slot] = i;
    }
}
// ---------------- K0e: per-group bounding boxes (1 warp / group) ----------------
__global__ __launch_bounds__(256) void boxes_kernel() {
    const int lane = threadIdx.x & 31;
    const int g = blockIdx.x * 8 + (threadIdx.x >> 5);
    const int base = g * GSZ + 2 * lane;
    float2 x2 = *(const float2*)&g_sx[base];
    float2 y2 = *(const float2*)&g_sy[base];
    float2 z2 = *(const float2*)&g_sz[base];
    unsigned mnx = __reduce_min_sync(0xffffffffu, min(__float_as_uint(x2.x), __float_as_uint(x2.y)));
    unsigned mxx = __reduce_max_sync(0xffffffffu, max(__float_as_uint(x2.x), __float_as_uint(x2.y)));
    unsigned mny = __reduce_min_sync(0xffffffffu, min(__float_as_uint(y2.x), __float_as_uint(y2.y)));
    unsigned mxy = __reduce_max_sync(0xffffffffu, max(__float_as_uint(y2.x), __float_as_uint(y2.y)));
    unsigned mnz = __reduce_min_sync(0xffffffffu, min(__float_as_uint(z2.x), __float_as_uint(z2.y)));
    unsigned mxz = __reduce_max_sync(0xffffffffu, max(__float_as_uint(z2.x), __float_as_uint(z2.y)));
    if (lane == 0) {
        g_boxa[g] = make_float4(__uint_as_float(mnx), __uint_as_float(mny),
                                __uint_as_float(mnz), 0.0f);
        g_boxb[g] = make_float4(__uint_as_float(mxx), __uint_as_float(mxy),
                                __uint_as_float(mxz), 0.0f);
    }
}

// ---------------- K1: FPS — R7 + register boxes/gmax + REDUX fast paths -------
// Warp w owns groups {j*16 + w} (interleaved -> balanced). Keys in regs:
// key = (min_d_bits<<32)|~orig_idx; u64 max = max d2, tie -> min original
// index == jnp.argmax. d2 = ((dx*dx+dy*dy)+dz*dz), RN ops, no FMA (bit-exact
// vs XLA). Group metadata lives in REGISTERS of lane j: static box (6 floats)
// + mutable gmax (refreshed via warp-uniform REDUX result, predicated move) —
// prune touches no memory. Per-group winner key/coords cached in smem at
// update time; warp best = 1 LDS + REDUX (lo-REDUX only on rare hi ties);
// global best = 1 LDS + REDUX post-barrier. One __syncthreads/step.
__global__ __launch_bounds__(512, 1) void fps_kernel() {
    extern __shared__ unsigned char smem_raw[];
    ull*    s_x2   = (ull*)smem_raw;               // [NPTS/2]  64KB
    ull*    s_y2   = s_x2 + NPTS / 2;              // 64KB
    ull*    s_z2   = s_y2 + NPTS / 2;              // 64KB
    ull*    s_gkey = s_z2 + NPTS / 2;              // [NGRP] owner-local phys
    float4* s_gwin = (float4*)(s_gkey + NGRP);     // [NGRP] owner-local argmax pt
    ull*    s_wkey = (ull*)(s_gwin + NGRP);        // [2][16]
    float4* s_wxyz = (float4*)(s_wkey + 32);       // [2][16]

    const int tid  = threadIdx.x;
    const int lane = tid & 31;
    const int w    = tid >> 5;

    // ---- stage coords into smem; keys into registers ----
    for (int i = tid; i < NPTS / 2; i += 512) {
        s_x2[i] = ((const ull*)g_sx)[i];
        s_y2[i] = ((const ull*)g_sy)[i];
        s_z2[i] = ((const ull*)g_sz)[i];
    }
    ull K0[GPW], K1[GPW];
#pragma unroll
    for (int j = 0; j < GPW; j++) {
        const int g = j * NW + w;                  // logical group (interleaved)
        const int p = g * GSZ + 2 * lane;
        int2 si = *(const int2*)&g_sidx[p];
        K0[j] = (0x7f7fffffULL << 32) | (unsigned)(~si.x);
        K1[j] = (0x7f7fffffULL << 32) | (unsigned)(~si.y);
    }
    // ---- lane j (<16) holds its group's box + gmax in registers ----
    float bnx = 0.f, bny = 0.f, bnz = 0.f, bxx = 0.f, bxy = 0.f, bxz = 0.f;
    float gmax = 3.402823466e38f;
    if (lane < GPW) {
        const int gl = lane * NW + w;              // logical group of phys w*16+lane
        float4 a = g_boxa[gl];
        float4 b = g_boxb[gl];
        bnx = a.x; bny = a.y; bnz = a.z;
        bxx = b.x; bxy = b.y; bxz = b.z;
    }
    if (tid < NGRP) {
        s_gkey[tid] = 0;
        s_gwin[tid] = make_float4(0.f, 0.f, 0.f, 0.f);
    }
    float cx = g_px[0], cy = g_py[0], cz = g_pz[0];
    if (tid == 0) { g_cx[0] = cx; g_cy[0] = cy; g_cz[0] = cz; }
    __syncthreads();

    int par = 0;
    for (int s = 0; s < NS - 1; s++) {
        // ---- prune: pure register math (no LDS) ----
        bool act = false;
        if (lane < GPW) {
            float dx = fmaxf(fmaxf(bnx - cx, cx - bxx), 0.0f);
            float dy = fmaxf(fmaxf(bny - cy, cy - bxy), 0.0f);
            float dz = fmaxf(fmaxf(bnz - cz, cz - bxz), 0.0f);
            float lb = dx * dx + dy * dy + dz * dz;
            act = (lb * 0.99999f - 1e-6f < gmax);
        }
        const unsigned amask = __ballot_sync(0xffffffffu, act);

        if (amask) {
            // ---- update active groups (keys in regs, coords via LDS) ----
            const unsigned nbx = __float_as_uint(-cx);
            const unsigned nby = __float_as_uint(-cy);
            const unsigned nbz = __float_as_uint(-cz);
            const ull nlx = pack2(nbx, nbx);
            const ull nly = pack2(nby, nby);
            const ull nlz = pack2(nbz, nbz);
#pragma unroll
            for (int j = 0; j < GPW; j++) {
                if ((amask >> j) & 1u) {           // warp-uniform branch
                    const int pp = (j * NW + w) * 32 + lane;   // point-pair idx
                    const ull X = s_x2[pp];
                    const ull Y = s_y2[pp];
                    const ull Z = s_z2[pp];
                    ull dx = f2_add(X, nlx);       // x - cx, exact RN
                    ull dy = f2_add(Y, nly);
                    ull dz = f2_add(Z, nlz);
                    ull d2 = f2_add(f2_add(f2_mul(dx, dx), f2_mul(dy, dy)), f2_mul(dz, dz));
                    unsigned d0, d1; unpack2(d0, d1, d2);
                    K0[j] = umin64(K0[j], ((ull)d0 << 32) | (unsigned)K0[j]);
                    K1[j] = umin64(K1[j], ((ull)d1 << 32) | (unsigned)K1[j]);
                    ull m = umax64(K0[j], K1[j]);
                    unsigned hi = (unsigned)(m >> 32);
                    unsigned gm = __reduce_max_sync(0xffffffffu, hi);
                    if (lane == j) gmax = __uint_as_float(gm);   // reg gmax refresh
                    unsigned cand = __ballot_sync(0xffffffffu, hi == gm);
                    bool win;
                    if (__popc(cand) == 1) {       // unique hi winner (common)
                        win = (hi == gm);
                    } else {                       // exact u64 tie-break on lo
                        unsigned lc = (hi == gm) ? (unsigned)m : 0u;
                        unsigned gl = __reduce_max_sync(0xffffffffu, lc);
                        unsigned wb = __ballot_sync(0xffffffffu, hi == gm && (unsigned)m == gl);
                        win = (lane == (__ffs(wb) - 1));
                    }
                    if (win) {                     // group argmax owner
                        const int ph = w * GPW + j;
                        const bool first = (m == K0[j]);
                        unsigned xl, xh, yl, yh, zl, zh;
                        unpack2(xl, xh, X); unpack2(yl, yh, Y); unpack2(zl, zh, Z);
                        s_gwin[ph] = make_float4(__uint_as_float(first ? xl : xh),
                                                 __uint_as_float(first ? yl : yh),
                                                 __uint_as_float(first ? zl : zh), 0.f);
                        s_gkey[ph] = m;
                    }
                }
            }
            __syncwarp();

            // ---- warp best over its 16 groups (owner-local LDS) ----
            ull kj = 0; float4 winc = make_float4(0.f, 0.f, 0.f, 0.f);
            if (lane < GPW) {
                const int ph = w * GPW + lane;
                kj = s_gkey[ph];
                winc = s_gwin[ph];
            }
            unsigned hi = (unsigned)(kj >> 32);
            unsigned gm = __reduce_max_sync(0xffffffffu, hi);
            unsigned cand = __ballot_sync(0xffffffffu, hi == gm);
            bool win;
            if (__popc(cand) == 1) {               // unique hi winner (common)
                win = (hi == gm);
            } else {
                unsigned lc = (hi == gm) ? (unsigned)kj : 0u;
                unsigned gl = __reduce_max_sync(0xffffffffu, lc);
                unsigned wb = __ballot_sync(0xffffffffu, hi == gm && (unsigned)kj == gl);
                win = (lane == (__ffs(wb) - 1));
            }
            if (win) {                             // unique winner lane
                s_wkey[par * 16 + w] = kj;
                s_wxyz[par * 16 + w] = winc;
            }
        } else {
            // ---- inactive: warp best provably unchanged; copy parity slot ----
            if (lane == 0) {
                s_wkey[par * 16 + w] = s_wkey[(par ^ 1) * 16 + w];
                s_wxyz[par * 16 + w] = s_wxyz[(par ^ 1) * 16 + w];
            }
        }
        __syncthreads();                           // the ONE barrier

        // ---- global best over 16 warp entries (computed by every warp) ----
        ull kw = (lane < 16) ? s_wkey[par * 16 + lane] : 0ULL;
        unsigned hi2 = (unsigned)(kw >> 32);
        unsigned gm2 = __reduce_max_sync(0xffffffffu, hi2);
        unsigned bal = __ballot_sync(0xffffffffu, hi2 == gm2);
        if (__popc(bal) != 1) {                    // rare hi tie across warps
            unsigned lc2 = (hi2 == gm2) ? (unsigned)kw : 0u;
            unsigned gl2 = __reduce_max_sync(0xffffffffu, lc2);
            bal = __ballot_sync(0xffffffffu, hi2 == gm2 && (unsigned)kw == gl2);
        }
        const int L = __ffs(bal) - 1;              // winning warp slot
        float4 c4 = s_wxyz[par * 16 + L];          // uniform LDS broadcast
        cx = c4.x; cy = c4.y; cz = c4.z;
        if (tid == 0) { g_cx[s + 1] = cx; g_cy[s + 1] = cy; g_cz[s + 1] = cz; }
        par ^= 1;                                  // next step: other buffer
    }
}

// ---------------- K2: top-10 nearest per center (1 warp / center) ----------------
__global__ __launch_bounds__(256) void topk_kernel() {
    const int lane = threadIdx.x & 31;
    const int w    = threadIdx.x >> 5;
    const int c    = blockIdx.x * 8 + w;
    const float cx = g_cx[c], cy = g_cy[c], cz = g_cz[c];

    ull heap[KNB];  // sorted ascending; key = (d2_bits<<32)|idx
#pragma unroll
    for (int q = 0; q < KNB; q++) heap[q] = ~0ULL;

#pragma unroll 4
    for (int i = 0; i < NPTS / 32; i++) {
        int p = lane + 32 * i;
        float dx = __fsub_rn(cx, __ldg(&g_px[p]));
        float dy = __fsub_rn(cy, __ldg(&g_py[p]));
        float dz = __fsub_rn(cz, __ldg(&g_pz[p]));
        float d2 = __fadd_rn(__fadd_rn(__fmul_rn(dx, dx), __fmul_rn(dy, dy)), __fmul_rn(dz, dz));
        ull key = ((ull)__float_as_uint(d2) << 32) | (unsigned)p;
        if (key < heap[KNB - 1]) {
            heap[KNB - 1] = key;
#pragma unroll
            for (int q = KNB - 1; q > 0; q--) {
                ull a = heap[q - 1], b = heap[q];
                heap[q - 1] = (a < b) ? a : b;
                heap[q]     = (a < b) ? b : a;
            }
        }
    }
#pragma unroll
    for (int r = 0; r < KNB; r++) {
        ull cur = heap[0];
        unsigned hi = (unsigned)(cur >> 32);
        unsigned mh = __reduce_min_sync(0xffffffffu, hi);
        unsigned lo = (hi == mh) ? (unsigned)cur : 0xffffffffu;
        unsigned ml = __reduce_min_sync(0xffffffffu, lo);
        if (hi == mh && (unsigned)cur == ml) {
#pragma unroll
            for (int q = 0; q < KNB - 1; q++) heap[q] = heap[q + 1];
            heap[KNB - 1] = ~0ULL;
        }
        if (lane == 0)
            g_src[c * KNB + r] = (__uint_as_float(mh) <= R2) ? (int)ml : -1;
    }
}

// ---------------- K3: MLP + masked segment max (CPB centers / block) ----------------
__global__ __launch_bounds__(128) void mlp_kernel(const float* __restrict__ W1,
                                                  const float* __restrict__ b1,
                                                  const float* __restrict__ W2,
                                                  const float* __restrict__ b2,
                                                  float* __restrict__ out) {
    const int c0 = blockIdx.x * CPB;
    const int t  = threadIdx.x;
    __shared__ float s_w2[64 * 128];
    __shared__ float s_hid[64];
    __shared__ int   s_src[CPB * KNB];

#pragma unroll
    for (int q = 0; q < 64; q++) s_w2[q * 128 + t] = W2[q * 128 + t];
    for (int i = t; i < CPB * KNB; i += 128) s_src[i] = g_src[c0 * KNB + i];

    float w1a = 0.f, w1b = 0.f, w1c = 0.f, bb1 = 0.f;
    if (t < 64) { w1a = W1[t]; w1b = W1[64 + t]; w1c = W1[128 + t]; bb1 = b1[t]; }
    const float b2c = b2[t];
    __syncthreads();

    for (int cc = 0; cc < CPB; cc++) {
        const int c = c0 + cc;
        const float bx = g_px[c], by = g_py[c], bz = g_pz[c];
        float acc = -3.402823466e38f;
        bool any = false;
        for (int nb = 0; nb < KNB; nb++) {
            int sp = s_src[cc * KNB + nb];
            if (sp >= 0) {
                any = true;
                if (t < 64) {
                    float rx = g_px[sp] - bx, ry = g_py[sp] - by, rz = g_pz[sp] - bz;
                    float h = bb1 + rx * w1a + ry * w1b + rz * w1c;
                    s_hid[t] = h > 0.f ? h : 0.f;
                }
                __syncthreads();
                float a = b2c;
#pragma unroll
                for (int k = 0; k < 64; k++) a = fmaf(s_hid[k], s_w2[k * 128 + t], a);
                acc = fmaxf(acc, a);
                __syncthreads();
            }
        }
        out[c * 128 + t] = any ? acc : 0.0f;
    }
}

// ---------------- K4: zero-fill rows NS..NPTS-1 ----------------
__global__ void fill_kernel(float* __restrict__ out) {
    int i = blockIdx.x * blockDim.x + threadIdx.x;
    if (i < (NPTS - NS) * 128) out[NS * 128 + i] = 0.0f;
}

// ---------------- launch ----------------
extern "C" void kernel_launch(void* const* d_in, const int* in_sizes, int n_in,
                              void* d_out, int out_size) {
    const float* pos = (const float*)d_in[0];
    const float* W1 = (const float*)d_in[2];
    const float* b1 = (const float*)d_in[3];
    const float* W2 = (const float*)d_in[4];
    const float* b2 = (const float*)d_in[5];
    float* out = (float*)d_out;

    prep_kernel<<<(NPTS + 255) / 256, 256>>>(pos);
    hist_kernel<<<(NPTS + 255) / 256, 256>>>();
    scan_kernel<<<1, NCELL>>>();
    scatter_kernel<<<(NPTS + 255) / 256, 256>>>();
    boxes_kernel<<<NGRP / 8, 256>>>();

    const int fps_smem = 3 * (NPTS / 2) * 8        // coords
                       + NGRP * 8                  // s_gkey
                       + NGRP * 16                 // s_gwin
                       + 32 * 8 + 32 * 16;         // s_wkey, s_wxyz
    cudaFuncSetAttribute(fps_kernel, cudaFuncAttributeMaxDynamicSharedMemorySize, fps_smem);
    fps_kernel<<<1, 512, fps_smem>>>();

    topk_kernel<<<NS / 8, 256>>>();

    mlp_kernel<<<NS / CPB, 128>>>(W1, b1, W2, b2, out);
    fill_kernel<<<((NPTS - NS) * 128 + 255) / 256, 256>>>(out);
}